// round 7
// baseline (speedup 1.0000x reference)
#include <cuda_runtime.h>
#include <cstdint>

// ---------------------------------------------------------------------------
// DeepLagrangianNetwork forward on GB300, fp32 with packed f32x2 FMA.
//   Z[b, r, :]  r=0: activations y;  r=1..7: dy/dq_{r-1}   (group of 8 rows)
//   1) layer1:   Z0 = relu(state@W_in+b), d1 = gate * W_in^T
//   2) gemm x2:  Zout = epilogue(Zin @ W_h); row-pair packed FFMA2, B
//                pre-duplicated in smem -> zero MOVs in inner loop
//   3) proj:     P = Z3 @ [W_g | W_ld | W_lo], register-prefetched staging
//   4) assemble: per-sample 7x7 Lagrangian algebra -> tau, M, C, G
// ---------------------------------------------------------------------------

#define N_DOF   7
#define WIDTH   1024
#define EPSR    1e-5f

__device__ float g_Z0[65536 * 1024];      // 256 MB
__device__ float g_Z1[65536 * 1024];      // 256 MB
__device__ float g_P [65536 * 32];        // 8 MB (29 cols padded to 32)

typedef unsigned long long ull;

// ---- packed f32x2 helpers (Blackwell) -------------------------------------
__device__ __forceinline__ ull dup2(float a) {
    ull r;
    asm("mov.b64 %0, {%1, %1};" : "=l"(r) : "f"(a));
    return r;
}
__device__ __forceinline__ void fma2(ull &d, ull a, ull b) {
    asm("fma.rn.f32x2 %0, %1, %2, %0;" : "+l"(d) : "l"(a), "l"(b));
}
__device__ __forceinline__ float2 unpack2(ull v) {
    float2 r;
    asm("mov.b64 {%0, %1}, %2;" : "=f"(r.x), "=f"(r.y) : "l"(v));
    return r;
}

// ---------------------------------------------------------------------------
// Kernel 1: input layer.
// ---------------------------------------------------------------------------
__global__ void __launch_bounds__(256)
layer1_kernel(const float* __restrict__ state,
              const float* __restrict__ W_in,
              const float* __restrict__ b_in,
              float* __restrict__ Z, int B)
{
    int g = blockIdx.x * blockDim.x + threadIdx.x;
    if (g >= B * WIDTH) return;
    int b = g >> 10;
    int o = g & (WIDTH - 1);

    float a = b_in[o];
    float wv[N_DOF];
#pragma unroll
    for (int i = 0; i < N_DOF; i++) {
        wv[i] = W_in[i * WIDTH + o];
        a = fmaf(state[b * N_DOF + i], wv[i], a);
    }
    size_t base = ((size_t)b * 8) * WIDTH + o;
    Z[base] = fmaxf(a, 0.f);
    float gate = (a > 0.f) ? 1.f : 0.f;
#pragma unroll
    for (int d = 0; d < N_DOF; d++)
        Z[base + (size_t)(1 + d) * WIDTH] = gate * wv[d];
}

// ---------------------------------------------------------------------------
// Kernel 2 (v3): fused hidden-layer GEMM, double-buffered, MOV-free inner loop.
// BM=BN=128, BK=16, 256 threads, 8x8 micro-tile.
//  - A packed as row-pairs straight from As[k][m] (m-contiguous ull loads)
//  - B pre-DUPLICATED at staging: Bs[k][2n]=Bs[k][2n+1]=W[k][n], so the
//    fma2 B operand is a direct ull load too.
// Per kk: 32 FFMA2 + 6 LDS.128, no dup2 MOVs.
// Accumulation order per output element identical to previous rounds.
// ---------------------------------------------------------------------------
__global__ void __launch_bounds__(256, 2)
gemm_fused_kernel(const float* __restrict__ Zin,
                  const float* __restrict__ W,
                  const float* __restrict__ bias,
                  float* __restrict__ Zout)
{
    __shared__ __align__(16) float As[2][16][128];   // 16 KB: As[buf][k][m]
    __shared__ __align__(16) float Bs[2][16][256];   // 32 KB: duplicated cols

    const int tid = threadIdx.x;
    const int tr  = tid >> 4;        // 0..15 (row slot: one sample group)
    const int tc  = tid & 15;        // 0..15 (col slot)
    const int rowBase = blockIdx.y * 128;
    const int colBase = blockIdx.x * 128;

    const float* gA = Zin + (size_t)rowBase * WIDTH;
    const float* gB = W + colBase;

    const int aR0 = tid >> 2,          aC0 = (tid & 3) * 4;
    const int aR1 = (tid + 256) >> 2,  aC1 = ((tid + 256) & 3) * 4;
    const int bR0 = tid >> 5,          bC0 = (tid & 31) * 4;   // rows 0..7
    const int bR1 = (tid + 256) >> 5,  bC1 = bC0;              // rows 8..15

    float4 a0, a1, b0, b1;

    // ---- prologue: tile 0 ----
    a0 = *reinterpret_cast<const float4*>(&gA[(size_t)aR0 * WIDTH + aC0]);
    a1 = *reinterpret_cast<const float4*>(&gA[(size_t)aR1 * WIDTH + aC1]);
    b0 = *reinterpret_cast<const float4*>(&gB[(size_t)bR0 * WIDTH + bC0]);
    b1 = *reinterpret_cast<const float4*>(&gB[(size_t)bR1 * WIDTH + bC1]);
    As[0][aC0 + 0][aR0] = a0.x; As[0][aC0 + 1][aR0] = a0.y;
    As[0][aC0 + 2][aR0] = a0.z; As[0][aC0 + 3][aR0] = a0.w;
    As[0][aC1 + 0][aR1] = a1.x; As[0][aC1 + 1][aR1] = a1.y;
    As[0][aC1 + 2][aR1] = a1.z; As[0][aC1 + 3][aR1] = a1.w;
    *reinterpret_cast<float4*>(&Bs[0][bR0][bC0 * 2])     = make_float4(b0.x, b0.x, b0.y, b0.y);
    *reinterpret_cast<float4*>(&Bs[0][bR0][bC0 * 2 + 4]) = make_float4(b0.z, b0.z, b0.w, b0.w);
    *reinterpret_cast<float4*>(&Bs[0][bR1][bC1 * 2])     = make_float4(b1.x, b1.x, b1.y, b1.y);
    *reinterpret_cast<float4*>(&Bs[0][bR1][bC1 * 2 + 4]) = make_float4(b1.z, b1.z, b1.w, b1.w);
    __syncthreads();

    // acc[i2][j]: packed rows (2*i2, 2*i2+1) of the thread's 8 rows, col j
    ull acc[4][8];
#pragma unroll
    for (int i = 0; i < 4; i++)
#pragma unroll
        for (int j = 0; j < 8; j++) acc[i][j] = 0ull;

    for (int t = 0; t < 64; t++) {
        const int p = t & 1;
        if (t < 63) {
            const int kt = (t + 1) * 16;
            a0 = *reinterpret_cast<const float4*>(&gA[(size_t)aR0 * WIDTH + kt + aC0]);
            a1 = *reinterpret_cast<const float4*>(&gA[(size_t)aR1 * WIDTH + kt + aC1]);
            b0 = *reinterpret_cast<const float4*>(&gB[(size_t)(kt + bR0) * WIDTH + bC0]);
            b1 = *reinterpret_cast<const float4*>(&gB[(size_t)(kt + bR1) * WIDTH + bC1]);
        }

        const float (*Asp)[128] = As[p];
        const float (*Bsp)[256] = Bs[p];
#pragma unroll
        for (int kk = 0; kk < 16; kk++) {
            const ull* ap = reinterpret_cast<const ull*>(&Asp[kk][tr * 8]);
            ull A0 = ap[0], A1 = ap[1], A2v = ap[2], A3 = ap[3];
            const ull* bp = reinterpret_cast<const ull*>(&Bsp[kk][tc * 16]);
            ull B0 = bp[0], B1 = bp[1], B2 = bp[2], B3 = bp[3];
            ull B4 = bp[4], B5 = bp[5], B6 = bp[6], B7 = bp[7];
#pragma unroll
            for (int j = 0; j < 8; j++) {
                ull Bj = (j == 0) ? B0 : (j == 1) ? B1 : (j == 2) ? B2 : (j == 3) ? B3
                       : (j == 4) ? B4 : (j == 5) ? B5 : (j == 6) ? B6 : B7;
                fma2(acc[0][j], A0,  Bj);
                fma2(acc[1][j], A1,  Bj);
                fma2(acc[2][j], A2v, Bj);
                fma2(acc[3][j], A3,  Bj);
            }
        }

        if (t < 63) {
            const int q = p ^ 1;
            As[q][aC0 + 0][aR0] = a0.x; As[q][aC0 + 1][aR0] = a0.y;
            As[q][aC0 + 2][aR0] = a0.z; As[q][aC0 + 3][aR0] = a0.w;
            As[q][aC1 + 0][aR1] = a1.x; As[q][aC1 + 1][aR1] = a1.y;
            As[q][aC1 + 2][aR1] = a1.z; As[q][aC1 + 3][aR1] = a1.w;
            *reinterpret_cast<float4*>(&Bs[q][bR0][bC0 * 2])     = make_float4(b0.x, b0.x, b0.y, b0.y);
            *reinterpret_cast<float4*>(&Bs[q][bR0][bC0 * 2 + 4]) = make_float4(b0.z, b0.z, b0.w, b0.w);
            *reinterpret_cast<float4*>(&Bs[q][bR1][bC1 * 2])     = make_float4(b1.x, b1.x, b1.y, b1.y);
            *reinterpret_cast<float4*>(&Bs[q][bR1][bC1 * 2 + 4]) = make_float4(b1.z, b1.z, b1.w, b1.w);
            __syncthreads();
        }
    }

    // --- epilogue: row 0 = bias+relu (gates), rows 1..7 gated ---
    const int grow0 = rowBase + tr * 8;
    const int col0  = colBase + tc * 8;

    float yv[8], gv[8];
#pragma unroll
    for (int j = 0; j < 8; j++) {
        float a0f = unpack2(acc[0][j]).x + bias[col0 + j];   // row 0
        yv[j] = fmaxf(a0f, 0.f);
        gv[j] = (a0f > 0.f) ? 1.f : 0.f;
    }
    {
        float4* p = reinterpret_cast<float4*>(&Zout[(size_t)grow0 * WIDTH + col0]);
        p[0] = make_float4(yv[0], yv[1], yv[2], yv[3]);
        p[1] = make_float4(yv[4], yv[5], yv[6], yv[7]);
    }
#pragma unroll
    for (int r = 1; r < 8; r++) {
        float ov[8];
#pragma unroll
        for (int j = 0; j < 8; j++) {
            float2 f = unpack2(acc[r >> 1][j]);
            float val = (r & 1) ? f.y : f.x;
            ov[j] = gv[j] * val;
        }
        float4* p = reinterpret_cast<float4*>(&Zout[(size_t)(grow0 + r) * WIDTH + col0]);
        p[0] = make_float4(ov[0], ov[1], ov[2], ov[3]);
        p[1] = make_float4(ov[4], ov[5], ov[6], ov[7]);
    }
}

// ---------------------------------------------------------------------------
// Kernel 3 (v3): head projection with register-prefetched staging.
// One row per thread (256 rows/block); next chunk's Z/W LDGs issued before
// the visibility barrier so compute hides their latency.
// Accumulation order (k ascending) identical to previous rounds.
// ---------------------------------------------------------------------------
__global__ void __launch_bounds__(256)
proj_kernel(const float* __restrict__ Z,
            const float* __restrict__ Wg,
            const float* __restrict__ Wld,
            const float* __restrict__ Wlo,
            float* __restrict__ P)
{
    __shared__ float Zs[256][33];                 // 33 KB, conflict-free
    __shared__ __align__(16) float Ws[32][32];    // 4 KB

    const int tid = threadIdx.x;
    const size_t rowBase = (size_t)blockIdx.x * 256;

    const int zR = tid >> 3;            // 0..31 (row group base /8)
    const int zC = (tid & 7) * 4;       // 0,4,..,28
    const int wK = tid >> 5;            // 0..7
    const int wC = tid & 31;            // 0..31

    ull acc2[16];
#pragma unroll
    for (int q = 0; q < 16; q++) acc2[q] = 0ull;

    // prefetch chunk 0
    float4 zr[8];
    float  wr[4];
#pragma unroll
    for (int t = 0; t < 8; t++)
        zr[t] = *reinterpret_cast<const float4*>(&Z[(rowBase + zR + 32 * t) * WIDTH + zC]);
#pragma unroll
    for (int t = 0; t < 4; t++) {
        int kk = wK + 8 * t;
        float wv = 0.f;
        if (wC == 0)      wv = Wg[kk];
        else if (wC < 8)  wv = Wld[kk * 7  + (wC - 1)];
        else if (wC < 29) wv = Wlo[kk * 21 + (wC - 8)];
        wr[t] = wv;
    }

    for (int c = 0; c < 32; c++) {          // 32 chunks of K=32
        __syncthreads();                    // readers of previous chunk done
        // store staged registers
#pragma unroll
        for (int t = 0; t < 8; t++) {
            int r = zR + 32 * t;
            Zs[r][zC + 0] = zr[t].x; Zs[r][zC + 1] = zr[t].y;
            Zs[r][zC + 2] = zr[t].z; Zs[r][zC + 3] = zr[t].w;
        }
#pragma unroll
        for (int t = 0; t < 4; t++) Ws[wK + 8 * t][wC] = wr[t];

        // prefetch next chunk (overlaps with compute below)
        if (c < 31) {
            const int k0n = (c + 1) * 32;
#pragma unroll
            for (int t = 0; t < 8; t++)
                zr[t] = *reinterpret_cast<const float4*>(
                    &Z[(rowBase + zR + 32 * t) * WIDTH + k0n + zC]);
#pragma unroll
            for (int t = 0; t < 4; t++) {
                int kk = k0n + wK + 8 * t;
                float wv = 0.f;
                if (wC == 0)      wv = Wg[kk];
                else if (wC < 8)  wv = Wld[kk * 7  + (wC - 1)];
                else if (wC < 29) wv = Wlo[kk * 21 + (wC - 8)];
                wr[t] = wv;
            }
        }
        __syncthreads();                    // chunk c visible

#pragma unroll
        for (int kk = 0; kk < 32; kk++) {
            ull z2 = dup2(Zs[tid][kk]);
            const ull* w2 = reinterpret_cast<const ull*>(&Ws[kk][0]);  // broadcast
#pragma unroll
            for (int q = 0; q < 16; q++) fma2(acc2[q], z2, w2[q]);
        }
    }

    float4* po = reinterpret_cast<float4*>(&P[(rowBase + tid) * 32]);
#pragma unroll
    for (int q = 0; q < 8; q++) {
        float2 f0 = unpack2(acc2[2 * q]);
        float2 f1 = unpack2(acc2[2 * q + 1]);
        po[q] = make_float4(f0.x, f0.y, f1.x, f1.y);
    }
}

// ---------------------------------------------------------------------------
// Kernel 4: per-sample Lagrangian assembly (unchanged algebra).
// Output: tau [B,7] | M [B,7,7] | C [B,7] | G [B,7]
// ---------------------------------------------------------------------------
__global__ void __launch_bounds__(256)
assemble_kernel(const float* __restrict__ P,
                const float* __restrict__ vel,
                const float* __restrict__ accel,
                const float* __restrict__ b_ld,
                const float* __restrict__ b_lo,
                float* __restrict__ out, int B)
{
    int b = blockIdx.x * blockDim.x + threadIdx.x;
    if (b >= B) return;

    constexpr int R[28] = {0,1,2,3,4,5,6, 1,2,3,4,5,6, 2,3,4,5,6, 3,4,5,6, 4,5,6, 5,6, 6};
    constexpr int Cc[28]= {0,1,2,3,4,5,6, 0,1,2,3,4,5, 0,1,2,3,4, 0,1,2,3, 0,1,2, 0,1, 0};

    const float* Pb = P + (size_t)b * 256;

    float v[7], ac[7];
#pragma unroll
    for (int d = 0; d < 7; d++) { v[d] = vel[b * 7 + d]; ac[d] = accel[b * 7 + d]; }

    float gate[7], lv[28];
#pragma unroll
    for (int o = 0; o < 7; o++) {
        float a = Pb[1 + o] + b_ld[o];
        gate[o] = (a > 0.f) ? 1.f : 0.f;
        lv[o]   = fmaxf(a, 0.f);
    }
#pragma unroll
    for (int j = 0; j < 21; j++) lv[7 + j] = Pb[8 + j] + b_lo[j];

    float w[7] = {0,0,0,0,0,0,0};
#pragma unroll
    for (int i = 0; i < 28; i++) w[Cc[i]] += lv[i] * v[R[i]];

    float dldt[28];
#pragma unroll
    for (int i = 0; i < 28; i++) dldt[i] = 0.f;
    float s[7], G[7];
#pragma unroll
    for (int d = 0; d < 7; d++) {
        const float* row = Pb + (size_t)(1 + d) * 32;
        G[d] = row[0];
        float sd = 0.f;
#pragma unroll
        for (int i = 0; i < 28; i++) {
            float e = row[1 + i];
            if (i < 7) e *= gate[i];
            dldt[i] = fmaf(e, v[d], dldt[i]);
            sd = fmaf(e, v[R[i]] * w[Cc[i]], sd);
        }
        s[d] = sd;
    }

    float p[7]  = {0,0,0,0,0,0,0};
    float lw[7] = {0,0,0,0,0,0,0};
#pragma unroll
    for (int i = 0; i < 28; i++) {
        p[Cc[i]]  += dldt[i] * v[R[i]];
        lw[R[i]]  += dldt[i] * w[Cc[i]];
    }
    float Lp[7] = {0,0,0,0,0,0,0};
    float u[7]  = {0,0,0,0,0,0,0};
#pragma unroll
    for (int i = 0; i < 28; i++) u[Cc[i]] += lv[i] * ac[R[i]];
    float Mq[7] = {0,0,0,0,0,0,0};
#pragma unroll
    for (int i = 0; i < 28; i++) {
        Lp[R[i]] += lv[i] * p[Cc[i]];
        Mq[R[i]] += lv[i] * u[Cc[i]];
    }

    const size_t B7 = (size_t)B * 7;
#pragma unroll
    for (int r = 0; r < 7; r++) {
        float Cr  = Lp[r] + lw[r] - s[r];
        float tau = Mq[r] + EPSR * ac[r] + Cr + G[r];
        out[(size_t)b * 7 + r]          = tau;
        out[B7 * 8 + (size_t)b * 7 + r] = Cr;
        out[B7 * 9 + (size_t)b * 7 + r] = G[r];
    }

    float Lm[7][7];
#pragma unroll
    for (int r = 0; r < 7; r++)
#pragma unroll
        for (int c = 0; c < 7; c++) Lm[r][c] = 0.f;
#pragma unroll
    for (int i = 0; i < 28; i++) Lm[R[i]][Cc[i]] = lv[i];

    float* Mout = out + B7 + (size_t)b * 49;
#pragma unroll
    for (int r = 0; r < 7; r++)
#pragma unroll
        for (int c = 0; c < 7; c++) {
            float m = (r == c) ? EPSR : 0.f;
#pragma unroll
            for (int t = 0; t < 7; t++) m = fmaf(Lm[r][t], Lm[c][t], m);
            Mout[r * 7 + c] = m;
        }
}

// ---------------------------------------------------------------------------
// kernel_launch — graph-capturable, allocation-free.
// ---------------------------------------------------------------------------
extern "C" void kernel_launch(void* const* d_in, const int* in_sizes, int n_in,
                              void* d_out, int out_size)
{
    const float* state  = (const float*)d_in[0];
    const float* vel    = (const float*)d_in[1];
    const float* accel  = (const float*)d_in[2];
    const float* W_in   = (const float*)d_in[3];
    const float* b_in   = (const float*)d_in[4];
    const float* W_h    = (const float*)d_in[5];
    const float* b_h    = (const float*)d_in[6];
    const float* W_g    = (const float*)d_in[7];
    // d_in[8] = b_g : unused (V never appears in outputs)
    const float* W_ld   = (const float*)d_in[9];
    const float* b_ld   = (const float*)d_in[10];
    const float* W_lo   = (const float*)d_in[11];
    const float* b_lo   = (const float*)d_in[12];

    const int B = in_sizes[0] / N_DOF;   // 8192
    const int Mrows = B * 8;             // 65536

    float *z0, *z1, *pp;
    cudaGetSymbolAddress((void**)&z0, g_Z0);
    cudaGetSymbolAddress((void**)&z1, g_Z1);
    cudaGetSymbolAddress((void**)&pp, g_P);

    // 1) input layer
    {
        int total = B * WIDTH;
        layer1_kernel<<<(total + 255) / 256, 256>>>(state, W_in, b_in, z0, B);
    }
    // 2) two fused hidden layers (ping-pong)
    {
        dim3 grid(WIDTH / 128, Mrows / 128);
        gemm_fused_kernel<<<grid, 256>>>(z0, W_h, b_h, z1);
        gemm_fused_kernel<<<grid, 256>>>(z1, W_h, b_h, z0);
    }
    // 3) head projections
    proj_kernel<<<Mrows / 256, 256>>>(z0, W_g, W_ld, W_lo, pp);
    // 4) per-sample assembly -> d_out
    assemble_kernel<<<(B + 255) / 256, 256>>>(pp, vel, accel, b_ld, b_lo,
                                              (float*)d_out, B);
}

// round 8
// speedup vs baseline: 3.3282x; 3.3282x over previous
#include <cuda_runtime.h>
#include <cstdint>

// ---------------------------------------------------------------------------
// DeepLagrangianNetwork forward on GB300, fp32 with packed f32x2 FMA.
//   Z[b, r, :]  r=0: activations y;  r=1..7: dy/dq_{r-1}   (group of 8 rows)
//   1) layer1:   Z0 = relu(state@W_in+b), d1 = gate * W_in^T
//   2) gemm x2:  Zout = epilogue(Zin @ W_h)  double-buffered; per-thread
//                cols split 4+4 (tc*4, 64+tc*4) -> conflict-free B LDS
//   3) proj:     P = Z3 @ [W_g | W_ld | W_lo], register-prefetched staging
//   4) assemble: per-sample 7x7 Lagrangian algebra -> tau, M, C, G
// ---------------------------------------------------------------------------

#define N_DOF   7
#define WIDTH   1024
#define EPSR    1e-5f

__device__ float g_Z0[65536 * 1024];      // 256 MB
__device__ float g_Z1[65536 * 1024];      // 256 MB
__device__ float g_P [65536 * 32];        // 8 MB (29 cols padded to 32)

typedef unsigned long long ull;

// ---- packed f32x2 helpers (Blackwell) -------------------------------------
__device__ __forceinline__ ull dup2(float a) {
    ull r;
    asm("mov.b64 %0, {%1, %1};" : "=l"(r) : "f"(a));
    return r;
}
__device__ __forceinline__ void fma2(ull &d, ull a, ull b) {
    asm("fma.rn.f32x2 %0, %1, %2, %0;" : "+l"(d) : "l"(a), "l"(b));
}
__device__ __forceinline__ float2 unpack2(ull v) {
    float2 r;
    asm("mov.b64 {%0, %1}, %2;" : "=f"(r.x), "=f"(r.y) : "l"(v));
    return r;
}

// ---------------------------------------------------------------------------
// Kernel 1: input layer.
// ---------------------------------------------------------------------------
__global__ void __launch_bounds__(256)
layer1_kernel(const float* __restrict__ state,
              const float* __restrict__ W_in,
              const float* __restrict__ b_in,
              float* __restrict__ Z, int B)
{
    int g = blockIdx.x * blockDim.x + threadIdx.x;
    if (g >= B * WIDTH) return;
    int b = g >> 10;
    int o = g & (WIDTH - 1);

    float a = b_in[o];
    float wv[N_DOF];
#pragma unroll
    for (int i = 0; i < N_DOF; i++) {
        wv[i] = W_in[i * WIDTH + o];
        a = fmaf(state[b * N_DOF + i], wv[i], a);
    }
    size_t base = ((size_t)b * 8) * WIDTH + o;
    Z[base] = fmaxf(a, 0.f);
    float gate = (a > 0.f) ? 1.f : 0.f;
#pragma unroll
    for (int d = 0; d < N_DOF; d++)
        Z[base + (size_t)(1 + d) * WIDTH] = gate * wv[d];
}

// ---------------------------------------------------------------------------
// Kernel 2 (v4 = R5 structure + conflict-free B reads):
// BM=BN=128, BK=16, 256 threads, 8 rows x (4+4) cols per thread.
// Thread cols: {tc*4 .. tc*4+3} and {64+tc*4 .. 64+tc*4+3}  -> B LDS.128
// sweeps are warp-contiguous 256B (no bank conflicts). A reads broadcast.
// Accumulation order per output element identical to R5 (bit-identical).
// ---------------------------------------------------------------------------
__global__ void __launch_bounds__(256, 2)
gemm_fused_kernel(const float* __restrict__ Zin,
                  const float* __restrict__ W,
                  const float* __restrict__ bias,
                  float* __restrict__ Zout)
{
    __shared__ __align__(16) float As[2][16][128];   // As[buf][k][m]
    __shared__ __align__(16) float Bs[2][16][128];   // Bs[buf][k][n]

    const int tid = threadIdx.x;
    const int tr  = tid >> 4;        // 0..15 (row slot: one sample group)
    const int tc  = tid & 15;        // 0..15 (col slot)
    const int rowBase = blockIdx.y * 128;
    const int colBase = blockIdx.x * 128;

    const float* gA = Zin + (size_t)rowBase * WIDTH;
    const float* gB = W + colBase;

    const int aR0 = tid >> 2,          aC0 = (tid & 3) * 4;
    const int aR1 = (tid + 256) >> 2,  aC1 = ((tid + 256) & 3) * 4;
    const int bR0 = tid >> 5,          bC0 = (tid & 31) * 4;
    const int bR1 = (tid + 256) >> 5,  bC1 = bC0;

    float4 a0, a1, b0, b1;

    // ---- prologue: tile 0 ----
    a0 = *reinterpret_cast<const float4*>(&gA[(size_t)aR0 * WIDTH + aC0]);
    a1 = *reinterpret_cast<const float4*>(&gA[(size_t)aR1 * WIDTH + aC1]);
    b0 = *reinterpret_cast<const float4*>(&gB[(size_t)bR0 * WIDTH + bC0]);
    b1 = *reinterpret_cast<const float4*>(&gB[(size_t)bR1 * WIDTH + bC1]);
    As[0][aC0 + 0][aR0] = a0.x; As[0][aC0 + 1][aR0] = a0.y;
    As[0][aC0 + 2][aR0] = a0.z; As[0][aC0 + 3][aR0] = a0.w;
    As[0][aC1 + 0][aR1] = a1.x; As[0][aC1 + 1][aR1] = a1.y;
    As[0][aC1 + 2][aR1] = a1.z; As[0][aC1 + 3][aR1] = a1.w;
    *reinterpret_cast<float4*>(&Bs[0][bR0][bC0]) = b0;
    *reinterpret_cast<float4*>(&Bs[0][bR1][bC1]) = b1;
    __syncthreads();

    // acc[i][j]: row i of the thread's 8 rows; j=0,1 -> col pairs in group0
    // (cols tc*4+{0,1},{2,3}); j=2,3 -> col pairs in group1 (64+tc*4+...).
    ull acc[8][4];
#pragma unroll
    for (int i = 0; i < 8; i++)
#pragma unroll
        for (int j = 0; j < 4; j++) acc[i][j] = 0ull;

    for (int t = 0; t < 64; t++) {
        const int p = t & 1;
        if (t < 63) {
            const int kt = (t + 1) * 16;
            a0 = *reinterpret_cast<const float4*>(&gA[(size_t)aR0 * WIDTH + kt + aC0]);
            a1 = *reinterpret_cast<const float4*>(&gA[(size_t)aR1 * WIDTH + kt + aC1]);
            b0 = *reinterpret_cast<const float4*>(&gB[(size_t)(kt + bR0) * WIDTH + bC0]);
            b1 = *reinterpret_cast<const float4*>(&gB[(size_t)(kt + bR1) * WIDTH + bC1]);
        }

        const float (*Asp)[128] = As[p];
        const float (*Bsp)[128] = Bs[p];
#pragma unroll
        for (int kk = 0; kk < 16; kk++) {
            float4 A0 = *reinterpret_cast<const float4*>(&Asp[kk][tr * 8]);      // broadcast
            float4 A1 = *reinterpret_cast<const float4*>(&Asp[kk][tr * 8 + 4]);  // broadcast
            const ull* bp0 = reinterpret_cast<const ull*>(&Bsp[kk][tc * 4]);      // 256B sweep
            const ull* bp1 = reinterpret_cast<const ull*>(&Bsp[kk][64 + tc * 4]); // 256B sweep
            ull B0 = bp0[0], B1 = bp0[1], B2 = bp1[0], B3 = bp1[1];
            ull A2[8] = { dup2(A0.x), dup2(A0.y), dup2(A0.z), dup2(A0.w),
                          dup2(A1.x), dup2(A1.y), dup2(A1.z), dup2(A1.w) };
#pragma unroll
            for (int i = 0; i < 8; i++) {
                fma2(acc[i][0], A2[i], B0);
                fma2(acc[i][1], A2[i], B1);
                fma2(acc[i][2], A2[i], B2);
                fma2(acc[i][3], A2[i], B3);
            }
        }

        if (t < 63) {
            const int q = p ^ 1;
            As[q][aC0 + 0][aR0] = a0.x; As[q][aC0 + 1][aR0] = a0.y;
            As[q][aC0 + 2][aR0] = a0.z; As[q][aC0 + 3][aR0] = a0.w;
            As[q][aC1 + 0][aR1] = a1.x; As[q][aC1 + 1][aR1] = a1.y;
            As[q][aC1 + 2][aR1] = a1.z; As[q][aC1 + 3][aR1] = a1.w;
            *reinterpret_cast<float4*>(&Bs[q][bR0][bC0]) = b0;
            *reinterpret_cast<float4*>(&Bs[q][bR1][bC1]) = b1;
            __syncthreads();
        }
    }

    // --- epilogue: row 0 = bias+relu (gates), rows 1..7 gated ---
    const int grow0 = rowBase + tr * 8;
    const int cg0   = colBase + tc * 4;        // group0 cols
    const int cg1   = colBase + 64 + tc * 4;   // group1 cols

    float yv[8], gv[8];   // [0..3] group0, [4..7] group1
#pragma unroll
    for (int j2 = 0; j2 < 2; j2++) {
        float2 f = unpack2(acc[0][j2]);
        float a0f = f.x + bias[cg0 + 2 * j2];
        float a1f = f.y + bias[cg0 + 2 * j2 + 1];
        yv[2 * j2]     = fmaxf(a0f, 0.f);
        yv[2 * j2 + 1] = fmaxf(a1f, 0.f);
        gv[2 * j2]     = (a0f > 0.f) ? 1.f : 0.f;
        gv[2 * j2 + 1] = (a1f > 0.f) ? 1.f : 0.f;
    }
#pragma unroll
    for (int j2 = 0; j2 < 2; j2++) {
        float2 f = unpack2(acc[0][2 + j2]);
        float a0f = f.x + bias[cg1 + 2 * j2];
        float a1f = f.y + bias[cg1 + 2 * j2 + 1];
        yv[4 + 2 * j2]     = fmaxf(a0f, 0.f);
        yv[4 + 2 * j2 + 1] = fmaxf(a1f, 0.f);
        gv[4 + 2 * j2]     = (a0f > 0.f) ? 1.f : 0.f;
        gv[4 + 2 * j2 + 1] = (a1f > 0.f) ? 1.f : 0.f;
    }
    {
        float* row = &Zout[(size_t)grow0 * WIDTH];
        *reinterpret_cast<float4*>(&row[cg0]) = make_float4(yv[0], yv[1], yv[2], yv[3]);
        *reinterpret_cast<float4*>(&row[cg1]) = make_float4(yv[4], yv[5], yv[6], yv[7]);
    }
#pragma unroll
    for (int r = 1; r < 8; r++) {
        float ov[8];
#pragma unroll
        for (int j2 = 0; j2 < 2; j2++) {
            float2 f = unpack2(acc[r][j2]);
            ov[2 * j2]     = gv[2 * j2]     * f.x;
            ov[2 * j2 + 1] = gv[2 * j2 + 1] * f.y;
        }
#pragma unroll
        for (int j2 = 0; j2 < 2; j2++) {
            float2 f = unpack2(acc[r][2 + j2]);
            ov[4 + 2 * j2]     = gv[4 + 2 * j2]     * f.x;
            ov[4 + 2 * j2 + 1] = gv[4 + 2 * j2 + 1] * f.y;
        }
        float* row = &Zout[(size_t)(grow0 + r) * WIDTH];
        *reinterpret_cast<float4*>(&row[cg0]) = make_float4(ov[0], ov[1], ov[2], ov[3]);
        *reinterpret_cast<float4*>(&row[cg1]) = make_float4(ov[4], ov[5], ov[6], ov[7]);
    }
}

// ---------------------------------------------------------------------------
// Kernel 3 (v3, kept from R6 — confirmed win): head projection.
// One row per thread (256 rows/block); register-prefetched staging.
// ---------------------------------------------------------------------------
__global__ void __launch_bounds__(256)
proj_kernel(const float* __restrict__ Z,
            const float* __restrict__ Wg,
            const float* __restrict__ Wld,
            const float* __restrict__ Wlo,
            float* __restrict__ P)
{
    __shared__ float Zs[256][33];                 // 33 KB, conflict-free
    __shared__ __align__(16) float Ws[32][32];    // 4 KB

    const int tid = threadIdx.x;
    const size_t rowBase = (size_t)blockIdx.x * 256;

    const int zR = tid >> 3;            // 0..31
    const int zC = (tid & 7) * 4;       // 0,4,..,28
    const int wK = tid >> 5;            // 0..7
    const int wC = tid & 31;            // 0..31

    ull acc2[16];
#pragma unroll
    for (int q = 0; q < 16; q++) acc2[q] = 0ull;

    float4 zr[8];
    float  wr[4];
#pragma unroll
    for (int t = 0; t < 8; t++)
        zr[t] = *reinterpret_cast<const float4*>(&Z[(rowBase + zR + 32 * t) * WIDTH + zC]);
#pragma unroll
    for (int t = 0; t < 4; t++) {
        int kk = wK + 8 * t;
        float wv = 0.f;
        if (wC == 0)      wv = Wg[kk];
        else if (wC < 8)  wv = Wld[kk * 7  + (wC - 1)];
        else if (wC < 29) wv = Wlo[kk * 21 + (wC - 8)];
        wr[t] = wv;
    }

    for (int c = 0; c < 32; c++) {
        __syncthreads();
#pragma unroll
        for (int t = 0; t < 8; t++) {
            int r = zR + 32 * t;
            Zs[r][zC + 0] = zr[t].x; Zs[r][zC + 1] = zr[t].y;
            Zs[r][zC + 2] = zr[t].z; Zs[r][zC + 3] = zr[t].w;
        }
#pragma unroll
        for (int t = 0; t < 4; t++) Ws[wK + 8 * t][wC] = wr[t];

        if (c < 31) {
            const int k0n = (c + 1) * 32;
#pragma unroll
            for (int t = 0; t < 8; t++)
                zr[t] = *reinterpret_cast<const float4*>(
                    &Z[(rowBase + zR + 32 * t) * WIDTH + k0n + zC]);
#pragma unroll
            for (int t = 0; t < 4; t++) {
                int kk = k0n + wK + 8 * t;
                float wv = 0.f;
                if (wC == 0)      wv = Wg[kk];
                else if (wC < 8)  wv = Wld[kk * 7  + (wC - 1)];
                else if (wC < 29) wv = Wlo[kk * 21 + (wC - 8)];
                wr[t] = wv;
            }
        }
        __syncthreads();

#pragma unroll
        for (int kk = 0; kk < 32; kk++) {
            ull z2 = dup2(Zs[tid][kk]);
            const ull* w2 = reinterpret_cast<const ull*>(&Ws[kk][0]);  // broadcast
#pragma unroll
            for (int q = 0; q < 16; q++) fma2(acc2[q], z2, w2[q]);
        }
    }

    float4* po = reinterpret_cast<float4*>(&P[(rowBase + tid) * 32]);
#pragma unroll
    for (int q = 0; q < 8; q++) {
        float2 f0 = unpack2(acc2[2 * q]);
        float2 f1 = unpack2(acc2[2 * q + 1]);
        po[q] = make_float4(f0.x, f0.y, f1.x, f1.y);
    }
}

// ---------------------------------------------------------------------------
// Kernel 4: per-sample Lagrangian assembly (unchanged algebra).
// Output: tau [B,7] | M [B,7,7] | C [B,7] | G [B,7]
// ---------------------------------------------------------------------------
__global__ void __launch_bounds__(256)
assemble_kernel(const float* __restrict__ P,
                const float* __restrict__ vel,
                const float* __restrict__ accel,
                const float* __restrict__ b_ld,
                const float* __restrict__ b_lo,
                float* __restrict__ out, int B)
{
    int b = blockIdx.x * blockDim.x + threadIdx.x;
    if (b >= B) return;

    constexpr int R[28] = {0,1,2,3,4,5,6, 1,2,3,4,5,6, 2,3,4,5,6, 3,4,5,6, 4,5,6, 5,6, 6};
    constexpr int Cc[28]= {0,1,2,3,4,5,6, 0,1,2,3,4,5, 0,1,2,3,4, 0,1,2,3, 0,1,2, 0,1, 0};

    const float* Pb = P + (size_t)b * 256;

    float v[7], ac[7];
#pragma unroll
    for (int d = 0; d < 7; d++) { v[d] = vel[b * 7 + d]; ac[d] = accel[b * 7 + d]; }

    float gate[7], lv[28];
#pragma unroll
    for (int o = 0; o < 7; o++) {
        float a = Pb[1 + o] + b_ld[o];
        gate[o] = (a > 0.f) ? 1.f : 0.f;
        lv[o]   = fmaxf(a, 0.f);
    }
#pragma unroll
    for (int j = 0; j < 21; j++) lv[7 + j] = Pb[8 + j] + b_lo[j];

    float w[7] = {0,0,0,0,0,0,0};
#pragma unroll
    for (int i = 0; i < 28; i++) w[Cc[i]] += lv[i] * v[R[i]];

    float dldt[28];
#pragma unroll
    for (int i = 0; i < 28; i++) dldt[i] = 0.f;
    float s[7], G[7];
#pragma unroll
    for (int d = 0; d < 7; d++) {
        const float* row = Pb + (size_t)(1 + d) * 32;
        G[d] = row[0];
        float sd = 0.f;
#pragma unroll
        for (int i = 0; i < 28; i++) {
            float e = row[1 + i];
            if (i < 7) e *= gate[i];
            dldt[i] = fmaf(e, v[d], dldt[i]);
            sd = fmaf(e, v[R[i]] * w[Cc[i]], sd);
        }
        s[d] = sd;
    }

    float p[7]  = {0,0,0,0,0,0,0};
    float lw[7] = {0,0,0,0,0,0,0};
#pragma unroll
    for (int i = 0; i < 28; i++) {
        p[Cc[i]]  += dldt[i] * v[R[i]];
        lw[R[i]]  += dldt[i] * w[Cc[i]];
    }
    float Lp[7] = {0,0,0,0,0,0,0};
    float u[7]  = {0,0,0,0,0,0,0};
#pragma unroll
    for (int i = 0; i < 28; i++) u[Cc[i]] += lv[i] * ac[R[i]];
    float Mq[7] = {0,0,0,0,0,0,0};
#pragma unroll
    for (int i = 0; i < 28; i++) {
        Lp[R[i]] += lv[i] * p[Cc[i]];
        Mq[R[i]] += lv[i] * u[Cc[i]];
    }

    const size_t B7 = (size_t)B * 7;
#pragma unroll
    for (int r = 0; r < 7; r++) {
        float Cr  = Lp[r] + lw[r] - s[r];
        float tau = Mq[r] + EPSR * ac[r] + Cr + G[r];
        out[(size_t)b * 7 + r]          = tau;
        out[B7 * 8 + (size_t)b * 7 + r] = Cr;
        out[B7 * 9 + (size_t)b * 7 + r] = G[r];
    }

    float Lm[7][7];
#pragma unroll
    for (int r = 0; r < 7; r++)
#pragma unroll
        for (int c = 0; c < 7; c++) Lm[r][c] = 0.f;
#pragma unroll
    for (int i = 0; i < 28; i++) Lm[R[i]][Cc[i]] = lv[i];

    float* Mout = out + B7 + (size_t)b * 49;
#pragma unroll
    for (int r = 0; r < 7; r++)
#pragma unroll
        for (int c = 0; c < 7; c++) {
            float m = (r == c) ? EPSR : 0.f;
#pragma unroll
            for (int t = 0; t < 7; t++) m = fmaf(Lm[r][t], Lm[c][t], m);
            Mout[r * 7 + c] = m;
        }
}

// ---------------------------------------------------------------------------
// kernel_launch — graph-capturable, allocation-free.
// ---------------------------------------------------------------------------
extern "C" void kernel_launch(void* const* d_in, const int* in_sizes, int n_in,
                              void* d_out, int out_size)
{
    const float* state  = (const float*)d_in[0];
    const float* vel    = (const float*)d_in[1];
    const float* accel  = (const float*)d_in[2];
    const float* W_in   = (const float*)d_in[3];
    const float* b_in   = (const float*)d_in[4];
    const float* W_h    = (const float*)d_in[5];
    const float* b_h    = (const float*)d_in[6];
    const float* W_g    = (const float*)d_in[7];
    // d_in[8] = b_g : unused (V never appears in outputs)
    const float* W_ld   = (const float*)d_in[9];
    const float* b_ld   = (const float*)d_in[10];
    const float* W_lo   = (const float*)d_in[11];
    const float* b_lo   = (const float*)d_in[12];

    const int B = in_sizes[0] / N_DOF;   // 8192
    const int Mrows = B * 8;             // 65536

    float *z0, *z1, *pp;
    cudaGetSymbolAddress((void**)&z0, g_Z0);
    cudaGetSymbolAddress((void**)&z1, g_Z1);
    cudaGetSymbolAddress((void**)&pp, g_P);

    // 1) input layer
    {
        int total = B * WIDTH;
        layer1_kernel<<<(total + 255) / 256, 256>>>(state, W_in, b_in, z0, B);
    }
    // 2) two fused hidden layers (ping-pong)
    {
        dim3 grid(WIDTH / 128, Mrows / 128);
        gemm_fused_kernel<<<grid, 256>>>(z0, W_h, b_h, z1);
        gemm_fused_kernel<<<grid, 256>>>(z1, W_h, b_h, z0);
    }
    // 3) head projections
    proj_kernel<<<Mrows / 256, 256>>>(z0, W_g, W_ld, W_lo, pp);
    // 4) per-sample assembly -> d_out
    assemble_kernel<<<(B + 255) / 256, 256>>>(pp, vel, accel, b_ld, b_lo,
                                              (float*)d_out, B);
}

// round 9
// speedup vs baseline: 3.3407x; 1.0038x over previous
#include <cuda_runtime.h>
#include <cstdint>

// ---------------------------------------------------------------------------
// DeepLagrangianNetwork forward on GB300, fp32 with packed f32x2 FMA.
//   Z[b, r, :]  r=0: activations y;  r=1..7: dy/dq_{r-1}   (group of 8 rows)
//   1) layer1:   Z0 = relu(state@W_in+b), d1 = gate * W_in^T
//   2) gemm x2:  Zout = epilogue(Zin @ W_h)  double-buffered; per-thread
//                cols split 4+4 (tc*4, 64+tc*4) -> conflict-free B LDS
//   3) proj:     P = Z3 @ [W_g | W_ld | W_lo], register-prefetched staging
//   4) assemble: per-sample 7x7 Lagrangian algebra -> tau, M, C, G
// ---------------------------------------------------------------------------

#define N_DOF   7
#define WIDTH   1024
#define EPSR    1e-5f

__device__ float g_Z0[65536 * 1024];      // 256 MB
__device__ float g_Z1[65536 * 1024];      // 256 MB
__device__ float g_P [65536 * 32];        // 8 MB (29 cols padded to 32)

typedef unsigned long long ull;

// ---- packed f32x2 helpers (Blackwell) -------------------------------------
__device__ __forceinline__ ull dup2(float a) {
    ull r;
    asm("mov.b64 %0, {%1, %1};" : "=l"(r) : "f"(a));
    return r;
}
__device__ __forceinline__ void fma2(ull &d, ull a, ull b) {
    asm("fma.rn.f32x2 %0, %1, %2, %0;" : "+l"(d) : "l"(a), "l"(b));
}
__device__ __forceinline__ float2 unpack2(ull v) {
    float2 r;
    asm("mov.b64 {%0, %1}, %2;" : "=f"(r.x), "=f"(r.y) : "l"(v));
    return r;
}

// ---------------------------------------------------------------------------
// Kernel 1: input layer.
// ---------------------------------------------------------------------------
__global__ void __launch_bounds__(256)
layer1_kernel(const float* __restrict__ state,
              const float* __restrict__ W_in,
              const float* __restrict__ b_in,
              float* __restrict__ Z, int B)
{
    int g = blockIdx.x * blockDim.x + threadIdx.x;
    if (g >= B * WIDTH) return;
    int b = g >> 10;
    int o = g & (WIDTH - 1);

    float a = b_in[o];
    float wv[N_DOF];
#pragma unroll
    for (int i = 0; i < N_DOF; i++) {
        wv[i] = W_in[i * WIDTH + o];
        a = fmaf(state[b * N_DOF + i], wv[i], a);
    }
    size_t base = ((size_t)b * 8) * WIDTH + o;
    Z[base] = fmaxf(a, 0.f);
    float gate = (a > 0.f) ? 1.f : 0.f;
#pragma unroll
    for (int d = 0; d < N_DOF; d++)
        Z[base + (size_t)(1 + d) * WIDTH] = gate * wv[d];
}

// ---------------------------------------------------------------------------
// Kernel 2 (v4 = R5 structure + conflict-free B reads):
// BM=BN=128, BK=16, 256 threads, 8 rows x (4+4) cols per thread.
// Thread cols: {tc*4 .. tc*4+3} and {64+tc*4 .. 64+tc*4+3}  -> B LDS.128
// sweeps are warp-contiguous 256B (no bank conflicts). A reads broadcast.
// Accumulation order per output element identical to R5 (bit-identical).
// ---------------------------------------------------------------------------
__global__ void __launch_bounds__(256, 2)
gemm_fused_kernel(const float* __restrict__ Zin,
                  const float* __restrict__ W,
                  const float* __restrict__ bias,
                  float* __restrict__ Zout)
{
    __shared__ __align__(16) float As[2][16][128];   // As[buf][k][m]
    __shared__ __align__(16) float Bs[2][16][128];   // Bs[buf][k][n]

    const int tid = threadIdx.x;
    const int tr  = tid >> 4;        // 0..15 (row slot: one sample group)
    const int tc  = tid & 15;        // 0..15 (col slot)
    const int rowBase = blockIdx.y * 128;
    const int colBase = blockIdx.x * 128;

    const float* gA = Zin + (size_t)rowBase * WIDTH;
    const float* gB = W + colBase;

    const int aR0 = tid >> 2,          aC0 = (tid & 3) * 4;
    const int aR1 = (tid + 256) >> 2,  aC1 = ((tid + 256) & 3) * 4;
    const int bR0 = tid >> 5,          bC0 = (tid & 31) * 4;
    const int bR1 = (tid + 256) >> 5,  bC1 = bC0;

    float4 a0, a1, b0, b1;

    // ---- prologue: tile 0 ----
    a0 = *reinterpret_cast<const float4*>(&gA[(size_t)aR0 * WIDTH + aC0]);
    a1 = *reinterpret_cast<const float4*>(&gA[(size_t)aR1 * WIDTH + aC1]);
    b0 = *reinterpret_cast<const float4*>(&gB[(size_t)bR0 * WIDTH + bC0]);
    b1 = *reinterpret_cast<const float4*>(&gB[(size_t)bR1 * WIDTH + bC1]);
    As[0][aC0 + 0][aR0] = a0.x; As[0][aC0 + 1][aR0] = a0.y;
    As[0][aC0 + 2][aR0] = a0.z; As[0][aC0 + 3][aR0] = a0.w;
    As[0][aC1 + 0][aR1] = a1.x; As[0][aC1 + 1][aR1] = a1.y;
    As[0][aC1 + 2][aR1] = a1.z; As[0][aC1 + 3][aR1] = a1.w;
    *reinterpret_cast<float4*>(&Bs[0][bR0][bC0]) = b0;
    *reinterpret_cast<float4*>(&Bs[0][bR1][bC1]) = b1;
    __syncthreads();

    // acc[i][j]: row i of the thread's 8 rows; j=0,1 -> col pairs in group0
    // (cols tc*4+{0,1},{2,3}); j=2,3 -> col pairs in group1 (64+tc*4+...).
    ull acc[8][4];
#pragma unroll
    for (int i = 0; i < 8; i++)
#pragma unroll
        for (int j = 0; j < 4; j++) acc[i][j] = 0ull;

    for (int t = 0; t < 64; t++) {
        const int p = t & 1;
        if (t < 63) {
            const int kt = (t + 1) * 16;
            a0 = *reinterpret_cast<const float4*>(&gA[(size_t)aR0 * WIDTH + kt + aC0]);
            a1 = *reinterpret_cast<const float4*>(&gA[(size_t)aR1 * WIDTH + kt + aC1]);
            b0 = *reinterpret_cast<const float4*>(&gB[(size_t)(kt + bR0) * WIDTH + bC0]);
            b1 = *reinterpret_cast<const float4*>(&gB[(size_t)(kt + bR1) * WIDTH + bC1]);
        }

        const float (*Asp)[128] = As[p];
        const float (*Bsp)[128] = Bs[p];
#pragma unroll
        for (int kk = 0; kk < 16; kk++) {
            float4 A0 = *reinterpret_cast<const float4*>(&Asp[kk][tr * 8]);      // broadcast
            float4 A1 = *reinterpret_cast<const float4*>(&Asp[kk][tr * 8 + 4]);  // broadcast
            const ull* bp0 = reinterpret_cast<const ull*>(&Bsp[kk][tc * 4]);      // 256B sweep
            const ull* bp1 = reinterpret_cast<const ull*>(&Bsp[kk][64 + tc * 4]); // 256B sweep
            ull B0 = bp0[0], B1 = bp0[1], B2 = bp1[0], B3 = bp1[1];
            ull A2[8] = { dup2(A0.x), dup2(A0.y), dup2(A0.z), dup2(A0.w),
                          dup2(A1.x), dup2(A1.y), dup2(A1.z), dup2(A1.w) };
#pragma unroll
            for (int i = 0; i < 8; i++) {
                fma2(acc[i][0], A2[i], B0);
                fma2(acc[i][1], A2[i], B1);
                fma2(acc[i][2], A2[i], B2);
                fma2(acc[i][3], A2[i], B3);
            }
        }

        if (t < 63) {
            const int q = p ^ 1;
            As[q][aC0 + 0][aR0] = a0.x; As[q][aC0 + 1][aR0] = a0.y;
            As[q][aC0 + 2][aR0] = a0.z; As[q][aC0 + 3][aR0] = a0.w;
            As[q][aC1 + 0][aR1] = a1.x; As[q][aC1 + 1][aR1] = a1.y;
            As[q][aC1 + 2][aR1] = a1.z; As[q][aC1 + 3][aR1] = a1.w;
            *reinterpret_cast<float4*>(&Bs[q][bR0][bC0]) = b0;
            *reinterpret_cast<float4*>(&Bs[q][bR1][bC1]) = b1;
            __syncthreads();
        }
    }

    // --- epilogue: row 0 = bias+relu (gates), rows 1..7 gated ---
    const int grow0 = rowBase + tr * 8;
    const int cg0   = colBase + tc * 4;        // group0 cols
    const int cg1   = colBase + 64 + tc * 4;   // group1 cols

    float yv[8], gv[8];   // [0..3] group0, [4..7] group1
#pragma unroll
    for (int j2 = 0; j2 < 2; j2++) {
        float2 f = unpack2(acc[0][j2]);
        float a0f = f.x + bias[cg0 + 2 * j2];
        float a1f = f.y + bias[cg0 + 2 * j2 + 1];
        yv[2 * j2]     = fmaxf(a0f, 0.f);
        yv[2 * j2 + 1] = fmaxf(a1f, 0.f);
        gv[2 * j2]     = (a0f > 0.f) ? 1.f : 0.f;
        gv[2 * j2 + 1] = (a1f > 0.f) ? 1.f : 0.f;
    }
#pragma unroll
    for (int j2 = 0; j2 < 2; j2++) {
        float2 f = unpack2(acc[0][2 + j2]);
        float a0f = f.x + bias[cg1 + 2 * j2];
        float a1f = f.y + bias[cg1 + 2 * j2 + 1];
        yv[4 + 2 * j2]     = fmaxf(a0f, 0.f);
        yv[4 + 2 * j2 + 1] = fmaxf(a1f, 0.f);
        gv[4 + 2 * j2]     = (a0f > 0.f) ? 1.f : 0.f;
        gv[4 + 2 * j2 + 1] = (a1f > 0.f) ? 1.f : 0.f;
    }
    {
        float* row = &Zout[(size_t)grow0 * WIDTH];
        *reinterpret_cast<float4*>(&row[cg0]) = make_float4(yv[0], yv[1], yv[2], yv[3]);
        *reinterpret_cast<float4*>(&row[cg1]) = make_float4(yv[4], yv[5], yv[6], yv[7]);
    }
#pragma unroll
    for (int r = 1; r < 8; r++) {
        float ov[8];
#pragma unroll
        for (int j2 = 0; j2 < 2; j2++) {
            float2 f = unpack2(acc[r][j2]);
            ov[2 * j2]     = gv[2 * j2]     * f.x;
            ov[2 * j2 + 1] = gv[2 * j2 + 1] * f.y;
        }
#pragma unroll
        for (int j2 = 0; j2 < 2; j2++) {
            float2 f = unpack2(acc[r][2 + j2]);
            ov[4 + 2 * j2]     = gv[4 + 2 * j2]     * f.x;
            ov[4 + 2 * j2 + 1] = gv[4 + 2 * j2 + 1] * f.y;
        }
        float* row = &Zout[(size_t)(grow0 + r) * WIDTH];
        *reinterpret_cast<float4*>(&row[cg0]) = make_float4(ov[0], ov[1], ov[2], ov[3]);
        *reinterpret_cast<float4*>(&row[cg1]) = make_float4(ov[4], ov[5], ov[6], ov[7]);
    }
}

// ---------------------------------------------------------------------------
// Kernel 3 (v3, kept from R6 — confirmed win): head projection.
// One row per thread (256 rows/block); register-prefetched staging.
// ---------------------------------------------------------------------------
__global__ void __launch_bounds__(256)
proj_kernel(const float* __restrict__ Z,
            const float* __restrict__ Wg,
            const float* __restrict__ Wld,
            const float* __restrict__ Wlo,
            float* __restrict__ P)
{
    __shared__ float Zs[256][33];                 // 33 KB, conflict-free
    __shared__ __align__(16) float Ws[32][32];    // 4 KB

    const int tid = threadIdx.x;
    const size_t rowBase = (size_t)blockIdx.x * 256;

    const int zR = tid >> 3;            // 0..31
    const int zC = (tid & 7) * 4;       // 0,4,..,28
    const int wK = tid >> 5;            // 0..7
    const int wC = tid & 31;            // 0..31

    ull acc2[16];
#pragma unroll
    for (int q = 0; q < 16; q++) acc2[q] = 0ull;

    float4 zr[8];
    float  wr[4];
#pragma unroll
    for (int t = 0; t < 8; t++)
        zr[t] = *reinterpret_cast<const float4*>(&Z[(rowBase + zR + 32 * t) * WIDTH + zC]);
#pragma unroll
    for (int t = 0; t < 4; t++) {
        int kk = wK + 8 * t;
        float wv = 0.f;
        if (wC == 0)      wv = Wg[kk];
        else if (wC < 8)  wv = Wld[kk * 7  + (wC - 1)];
        else if (wC < 29) wv = Wlo[kk * 21 + (wC - 8)];
        wr[t] = wv;
    }

    for (int c = 0; c < 32; c++) {
        __syncthreads();
#pragma unroll
        for (int t = 0; t < 8; t++) {
            int r = zR + 32 * t;
            Zs[r][zC + 0] = zr[t].x; Zs[r][zC + 1] = zr[t].y;
            Zs[r][zC + 2] = zr[t].z; Zs[r][zC + 3] = zr[t].w;
        }
#pragma unroll
        for (int t = 0; t < 4; t++) Ws[wK + 8 * t][wC] = wr[t];

        if (c < 31) {
            const int k0n = (c + 1) * 32;
#pragma unroll
            for (int t = 0; t < 8; t++)
                zr[t] = *reinterpret_cast<const float4*>(
                    &Z[(rowBase + zR + 32 * t) * WIDTH + k0n + zC]);
#pragma unroll
            for (int t = 0; t < 4; t++) {
                int kk = k0n + wK + 8 * t;
                float wv = 0.f;
                if (wC == 0)      wv = Wg[kk];
                else if (wC < 8)  wv = Wld[kk * 7  + (wC - 1)];
                else if (wC < 29) wv = Wlo[kk * 21 + (wC - 8)];
                wr[t] = wv;
            }
        }
        __syncthreads();

#pragma unroll
        for (int kk = 0; kk < 32; kk++) {
            ull z2 = dup2(Zs[tid][kk]);
            const ull* w2 = reinterpret_cast<const ull*>(&Ws[kk][0]);  // broadcast
#pragma unroll
            for (int q = 0; q < 16; q++) fma2(acc2[q], z2, w2[q]);
        }
    }

    float4* po = reinterpret_cast<float4*>(&P[(rowBase + tid) * 32]);
#pragma unroll
    for (int q = 0; q < 8; q++) {
        float2 f0 = unpack2(acc2[2 * q]);
        float2 f1 = unpack2(acc2[2 * q + 1]);
        po[q] = make_float4(f0.x, f0.y, f1.x, f1.y);
    }
}

// ---------------------------------------------------------------------------
// Kernel 4: per-sample Lagrangian assembly (unchanged algebra).
// Output: tau [B,7] | M [B,7,7] | C [B,7] | G [B,7]
// ---------------------------------------------------------------------------
__global__ void __launch_bounds__(256)
assemble_kernel(const float* __restrict__ P,
                const float* __restrict__ vel,
                const float* __restrict__ accel,
                const float* __restrict__ b_ld,
                const float* __restrict__ b_lo,
                float* __restrict__ out, int B)
{
    int b = blockIdx.x * blockDim.x + threadIdx.x;
    if (b >= B) return;

    constexpr int R[28] = {0,1,2,3,4,5,6, 1,2,3,4,5,6, 2,3,4,5,6, 3,4,5,6, 4,5,6, 5,6, 6};
    constexpr int Cc[28]= {0,1,2,3,4,5,6, 0,1,2,3,4,5, 0,1,2,3,4, 0,1,2,3, 0,1,2, 0,1, 0};

    const float* Pb = P + (size_t)b * 256;

    float v[7], ac[7];
#pragma unroll
    for (int d = 0; d < 7; d++) { v[d] = vel[b * 7 + d]; ac[d] = accel[b * 7 + d]; }

    float gate[7], lv[28];
#pragma unroll
    for (int o = 0; o < 7; o++) {
        float a = Pb[1 + o] + b_ld[o];
        gate[o] = (a > 0.f) ? 1.f : 0.f;
        lv[o]   = fmaxf(a, 0.f);
    }
#pragma unroll
    for (int j = 0; j < 21; j++) lv[7 + j] = Pb[8 + j] + b_lo[j];

    float w[7] = {0,0,0,0,0,0,0};
#pragma unroll
    for (int i = 0; i < 28; i++) w[Cc[i]] += lv[i] * v[R[i]];

    float dldt[28];
#pragma unroll
    for (int i = 0; i < 28; i++) dldt[i] = 0.f;
    float s[7], G[7];
#pragma unroll
    for (int d = 0; d < 7; d++) {
        const float* row = Pb + (size_t)(1 + d) * 32;
        G[d] = row[0];
        float sd = 0.f;
#pragma unroll
        for (int i = 0; i < 28; i++) {
            float e = row[1 + i];
            if (i < 7) e *= gate[i];
            dldt[i] = fmaf(e, v[d], dldt[i]);
            sd = fmaf(e, v[R[i]] * w[Cc[i]], sd);
        }
        s[d] = sd;
    }

    float p[7]  = {0,0,0,0,0,0,0};
    float lw[7] = {0,0,0,0,0,0,0};
#pragma unroll
    for (int i = 0; i < 28; i++) {
        p[Cc[i]]  += dldt[i] * v[R[i]];
        lw[R[i]]  += dldt[i] * w[Cc[i]];
    }
    float Lp[7] = {0,0,0,0,0,0,0};
    float u[7]  = {0,0,0,0,0,0,0};
#pragma unroll
    for (int i = 0; i < 28; i++) u[Cc[i]] += lv[i] * ac[R[i]];
    float Mq[7] = {0,0,0,0,0,0,0};
#pragma unroll
    for (int i = 0; i < 28; i++) {
        Lp[R[i]] += lv[i] * p[Cc[i]];
        Mq[R[i]] += lv[i] * u[Cc[i]];
    }

    const size_t B7 = (size_t)B * 7;
#pragma unroll
    for (int r = 0; r < 7; r++) {
        float Cr  = Lp[r] + lw[r] - s[r];
        float tau = Mq[r] + EPSR * ac[r] + Cr + G[r];
        out[(size_t)b * 7 + r]          = tau;
        out[B7 * 8 + (size_t)b * 7 + r] = Cr;
        out[B7 * 9 + (size_t)b * 7 + r] = G[r];
    }

    float Lm[7][7];
#pragma unroll
    for (int r = 0; r < 7; r++)
#pragma unroll
        for (int c = 0; c < 7; c++) Lm[r][c] = 0.f;
#pragma unroll
    for (int i = 0; i < 28; i++) Lm[R[i]][Cc[i]] = lv[i];

    float* Mout = out + B7 + (size_t)b * 49;
#pragma unroll
    for (int r = 0; r < 7; r++)
#pragma unroll
        for (int c = 0; c < 7; c++) {
            float m = (r == c) ? EPSR : 0.f;
#pragma unroll
            for (int t = 0; t < 7; t++) m = fmaf(Lm[r][t], Lm[c][t], m);
            Mout[r * 7 + c] = m;
        }
}

// ---------------------------------------------------------------------------
// kernel_launch — graph-capturable, allocation-free.
// ---------------------------------------------------------------------------
extern "C" void kernel_launch(void* const* d_in, const int* in_sizes, int n_in,
                              void* d_out, int out_size)
{
    const float* state  = (const float*)d_in[0];
    const float* vel    = (const float*)d_in[1];
    const float* accel  = (const float*)d_in[2];
    const float* W_in   = (const float*)d_in[3];
    const float* b_in   = (const float*)d_in[4];
    const float* W_h    = (const float*)d_in[5];
    const float* b_h    = (const float*)d_in[6];
    const float* W_g    = (const float*)d_in[7];
    // d_in[8] = b_g : unused (V never appears in outputs)
    const float* W_ld   = (const float*)d_in[9];
    const float* b_ld   = (const float*)d_in[10];
    const float* W_lo   = (const float*)d_in[11];
    const float* b_lo   = (const float*)d_in[12];

    const int B = in_sizes[0] / N_DOF;   // 8192
    const int Mrows = B * 8;             // 65536

    float *z0, *z1, *pp;
    cudaGetSymbolAddress((void**)&z0, g_Z0);
    cudaGetSymbolAddress((void**)&z1, g_Z1);
    cudaGetSymbolAddress((void**)&pp, g_P);

    // 1) input layer
    {
        int total = B * WIDTH;
        layer1_kernel<<<(total + 255) / 256, 256>>>(state, W_in, b_in, z0, B);
    }
    // 2) two fused hidden layers (ping-pong)
    {
        dim3 grid(WIDTH / 128, Mrows / 128);
        gemm_fused_kernel<<<grid, 256>>>(z0, W_h, b_h, z1);
        gemm_fused_kernel<<<grid, 256>>>(z1, W_h, b_h, z0);
    }
    // 3) head projections
    proj_kernel<<<Mrows / 256, 256>>>(z0, W_g, W_ld, W_lo, pp);
    // 4) per-sample assembly -> d_out
    assemble_kernel<<<(B + 255) / 256, 256>>>(pp, vel, accel, b_ld, b_lo,
                                              (float*)d_out, B);
}